// round 4
// baseline (speedup 1.0000x reference)
#include <cuda_runtime.h>
#include <math.h>

#define NMAX 50000
#define EMAX 800000
#define GSEG 64

// ---------------- scratch (device globals; zero-initialized at module load) ----------------
__device__ float g_h[NMAX * 128];      // GAT-transformed features
__device__ float g_asrc[NMAX * 4];     // per-node attention logits (src part)
__device__ float g_adst[NMAX * 4];     // per-node attention logits (dst part)
__device__ float g_out1[NMAX * 128];   // GAT output
__device__ float g_h2[NMAX * 128];     // out1 @ W_gcn
__device__ float g_out2[NMAX * 128];   // GCN output
__device__ float g_dinv[NMAX];         // 1/sqrt(deg)
__device__ float g_eg[NMAX];           // exp(gate) per node
__device__ int   g_deg[NMAX];          // degree counts (zeroed by tail of pipeline)
__device__ int   g_rowptr[NMAX + 1];   // CSR row pointers (by dst)
__device__ int   g_wpos[NMAX];         // fill cursors
__device__ int   g_col[EMAX + NMAX];   // CSR column (src node ids)
__device__ int   g_segstart[GSEG + 1]; // graph segment boundaries (batch sorted)

__device__ __forceinline__ float lrelu(float v) { return fmaxf(v, 0.2f * v); }
__device__ __forceinline__ float elu(float v) { return v > 0.f ? v : __expf(v) - 1.f; }

// packed fp32x2 helpers (Blackwell)
__device__ __forceinline__ unsigned long long pack2(float x, float y) {
    unsigned long long r;
    asm("mov.b64 %0, {%1, %2};" : "=l"(r) : "f"(x), "f"(y));
    return r;
}
__device__ __forceinline__ float2 unpack2(unsigned long long v) {
    float2 r;
    asm("mov.b64 {%0, %1}, %2;" : "=f"(r.x), "=f"(r.y) : "l"(v));
    return r;
}
__device__ __forceinline__ unsigned long long fma2(unsigned long long a,
                                                   unsigned long long b,
                                                   unsigned long long c) {
    unsigned long long d;
    asm("fma.rn.f32x2 %0, %1, %2, %3;" : "=l"(d) : "l"(a), "l"(b), "l"(c));
    return d;
}

// ---------------- CSR: count degrees (g_deg is zero on entry every launch) ----------------
__global__ void k_count(const int* __restrict__ ei, int E) {
    int i = blockIdx.x * blockDim.x + threadIdx.x;
    if (i < E) atomicAdd(&g_deg[__ldg(ei + E + i)], 1);
}

// scan: rowptr (deg+1 incl self loop), self loop at slot 0, dinv + segstart fused
__global__ void k_scan(const int* __restrict__ batch, int N) {
    __shared__ int part[1024];
    int tid = threadIdx.x;
    int chunk = (N + 1023) >> 10;
    int s0 = tid * chunk, e0 = min(s0 + chunk, N);
    int s = 0;
    for (int i = s0; i < e0; i++) {
        s += g_deg[i] + 1;
        // segment boundaries (batch sorted ascending)
        int b = batch[i];
        int pb = (i == 0) ? -1 : batch[i - 1];
        for (int g = pb + 1; g <= b; g++) g_segstart[g] = i;
        if (i == N - 1)
            for (int g = b + 1; g <= GSEG; g++) g_segstart[g] = N;
    }
    part[tid] = s;
    __syncthreads();
    for (int off = 1; off < 1024; off <<= 1) {
        int v = (tid >= off) ? part[tid - off] : 0;
        __syncthreads();
        part[tid] += v;
        __syncthreads();
    }
    int base = (tid == 0) ? 0 : part[tid - 1];
    for (int i = s0; i < e0; i++) {
        int rd = g_deg[i] + 1;
        g_rowptr[i] = base;
        g_col[base] = i;        // self loop in slot 0
        g_wpos[i] = base + 1;   // edges fill after
        g_dinv[i] = rsqrtf((float)rd);
        base += rd;
    }
    if (tid == 1023) g_rowptr[N] = part[1023];
}

__global__ void k_fill(const int* __restrict__ ei, int E) {
    int i = blockIdx.x * blockDim.x + threadIdx.x;
    if (i >= E) return;
    int s = __ldg(ei + i);
    int d = __ldg(ei + E + i);
    int pos = atomicAdd(&g_wpos[d], 1);
    g_col[pos] = s;
}

// ---------------- GEMM: C[N,128] = A[N,128] @ B[128,128], fp32, packed f32x2 ----------------
__global__ void gemm128(const float* __restrict__ A, const float* __restrict__ B,
                        float* __restrict__ C, int nrows) {
    __shared__ float As[8][128];  // [k][row]
    __shared__ float Bs[8][128];  // [k][col]
    int tid = threadIdx.x;
    int ty = tid >> 4;            // 0..15
    int tx = tid & 15;            // 0..15
    int row0 = blockIdx.x * 128;

    unsigned long long acc[8][4];
#pragma unroll
    for (int i = 0; i < 8; i++)
#pragma unroll
        for (int j = 0; j < 4; j++) acc[i][j] = 0ULL;

    int ar = tid >> 1;
    int ac = (tid & 1) * 4;
    int bk = tid >> 5;
    int bc = (tid & 31) * 4;

    for (int k0 = 0; k0 < 128; k0 += 8) {
        float4 av = make_float4(0.f, 0.f, 0.f, 0.f);
        if (row0 + ar < nrows)
            av = *(const float4*)(A + (long long)(row0 + ar) * 128 + k0 + ac);
        float4 bv = *(const float4*)(B + (long long)(k0 + bk) * 128 + bc);
        __syncthreads();
        As[ac + 0][ar] = av.x; As[ac + 1][ar] = av.y;
        As[ac + 2][ar] = av.z; As[ac + 3][ar] = av.w;
        *(float4*)(&Bs[bk][bc]) = bv;
        __syncthreads();
#pragma unroll
        for (int kk = 0; kk < 8; kk++) {
            float4 a0 = *(const float4*)(&As[kk][ty * 4]);
            float4 a1 = *(const float4*)(&As[kk][ty * 4 + 64]);
            ulonglong2 bl = *(const ulonglong2*)(&Bs[kk][tx * 4]);
            ulonglong2 bh = *(const ulonglong2*)(&Bs[kk][tx * 4 + 64]);
            unsigned long long bb[4] = {bl.x, bl.y, bh.x, bh.y};
            float a[8] = {a0.x, a0.y, a0.z, a0.w, a1.x, a1.y, a1.z, a1.w};
#pragma unroll
            for (int i = 0; i < 8; i++) {
                unsigned long long ad = pack2(a[i], a[i]);
#pragma unroll
                for (int j = 0; j < 4; j++) acc[i][j] = fma2(ad, bb[j], acc[i][j]);
            }
        }
    }
#pragma unroll
    for (int i = 0; i < 8; i++) {
        int r = row0 + ty * 4 + (i < 4 ? i : 60 + i);
        if (r < nrows) {
            float2 p0 = unpack2(acc[i][0]);
            float2 p1 = unpack2(acc[i][1]);
            float2 p2 = unpack2(acc[i][2]);
            float2 p3 = unpack2(acc[i][3]);
            *(float4*)(C + (long long)r * 128 + tx * 4) =
                make_float4(p0.x, p0.y, p1.x, p1.y);
            *(float4*)(C + (long long)r * 128 + tx * 4 + 64) =
                make_float4(p2.x, p2.y, p3.x, p3.y);
        }
    }
}

// ---------------- attention logits per node/head ----------------
__global__ void k_attn(const float* __restrict__ att_src,
                       const float* __restrict__ att_dst, int N) {
    int t = blockIdx.x * blockDim.x + threadIdx.x;
    if (t >= N * 4) return;
    int n = t >> 2, hd = t & 3;
    const float* hp = g_h + (long long)n * 128 + hd * 32;
    float s1 = 0.f, s2 = 0.f;
#pragma unroll
    for (int c = 0; c < 32; c += 4) {
        float4 hv = *(const float4*)(hp + c);
        float4 as = *(const float4*)(att_src + hd * 32 + c);
        float4 ad = *(const float4*)(att_dst + hd * 32 + c);
        s1 += hv.x * as.x + hv.y * as.y + hv.z * as.z + hv.w * as.w;
        s2 += hv.x * ad.x + hv.y * ad.y + hv.z * ad.z + hv.w * ad.w;
    }
    g_asrc[t] = s1;
    g_adst[t] = s2;
}

// ---------------- GAT aggregation: warp per dst node, single pass, MLP=4 ----------------
__global__ void k_gat_agg(const float* __restrict__ b_gat,
                          const float* __restrict__ bn_w,
                          const float* __restrict__ bn_b, int N) {
    int t = blockIdx.x * blockDim.x + threadIdx.x;
    int node = t >> 5, lane = t & 31;
    if (node >= N) return;
    int head = lane >> 3;
    int beg = g_rowptr[node], end = g_rowptr[node + 1];
    float adh = g_adst[node * 4 + head];

    float4 acc = make_float4(0.f, 0.f, 0.f, 0.f);
    float den = 0.f;
    int i = beg;
    for (; i + 4 <= end; i += 4) {
        int s0 = __ldg(&g_col[i + 0]);
        int s1 = __ldg(&g_col[i + 1]);
        int s2 = __ldg(&g_col[i + 2]);
        int s3 = __ldg(&g_col[i + 3]);
        float a0 = __ldg(&g_asrc[s0 * 4 + head]);
        float a1 = __ldg(&g_asrc[s1 * 4 + head]);
        float a2 = __ldg(&g_asrc[s2 * 4 + head]);
        float a3 = __ldg(&g_asrc[s3 * 4 + head]);
        float4 h0 = *(const float4*)(g_h + (long long)s0 * 128 + lane * 4);
        float4 h1 = *(const float4*)(g_h + (long long)s1 * 128 + lane * 4);
        float4 h2 = *(const float4*)(g_h + (long long)s2 * 128 + lane * 4);
        float4 h3 = *(const float4*)(g_h + (long long)s3 * 128 + lane * 4);
        float e0 = __expf(lrelu(a0 + adh));
        float e1 = __expf(lrelu(a1 + adh));
        float e2 = __expf(lrelu(a2 + adh));
        float e3 = __expf(lrelu(a3 + adh));
        den += (e0 + e1) + (e2 + e3);
        acc.x += e0 * h0.x + e1 * h1.x + e2 * h2.x + e3 * h3.x;
        acc.y += e0 * h0.y + e1 * h1.y + e2 * h2.y + e3 * h3.y;
        acc.z += e0 * h0.z + e1 * h1.z + e2 * h2.z + e3 * h3.z;
        acc.w += e0 * h0.w + e1 * h1.w + e2 * h2.w + e3 * h3.w;
    }
    for (; i < end; i++) {
        int s = __ldg(&g_col[i]);
        float a = __ldg(&g_asrc[s * 4 + head]);
        float e = __expf(lrelu(a + adh));
        den += e;
        float4 hv = *(const float4*)(g_h + (long long)s * 128 + lane * 4);
        acc.x += e * hv.x; acc.y += e * hv.y;
        acc.z += e * hv.z; acc.w += e * hv.w;
    }
    float inv = 1.f / (den + 1e-16f);
    int c4 = lane * 4;
    float4 bg = *(const float4*)(b_gat + c4);
    float4 wv = *(const float4*)(bn_w + c4);
    float4 bv = *(const float4*)(bn_b + c4);
    acc.x = elu(acc.x * inv + bg.x) * wv.x + bv.x;
    acc.y = elu(acc.y * inv + bg.y) * wv.y + bv.y;
    acc.z = elu(acc.z * inv + bg.z) * wv.z + bv.z;
    acc.w = elu(acc.w * inv + bg.w) * wv.w + bv.w;
    *(float4*)(g_out1 + (long long)node * 128 + c4) = acc;
}

// ---------------- GCN aggregation + post + gate, MLP=4 ----------------
__global__ void k_gcn_agg(const float* __restrict__ b_gcn,
                          const float* __restrict__ bn_w,
                          const float* __restrict__ bn_b,
                          const float* __restrict__ W_gate,
                          const float* __restrict__ b_gate, int N) {
    int t = blockIdx.x * blockDim.x + threadIdx.x;
    int node = t >> 5, lane = t & 31;
    if (node >= N) return;
    int beg = g_rowptr[node], end = g_rowptr[node + 1];

    float4 acc = make_float4(0.f, 0.f, 0.f, 0.f);
    int i = beg;
    for (; i + 4 <= end; i += 4) {
        int s0 = __ldg(&g_col[i + 0]);
        int s1 = __ldg(&g_col[i + 1]);
        int s2 = __ldg(&g_col[i + 2]);
        int s3 = __ldg(&g_col[i + 3]);
        float d0 = __ldg(&g_dinv[s0]);
        float d1 = __ldg(&g_dinv[s1]);
        float d2 = __ldg(&g_dinv[s2]);
        float d3 = __ldg(&g_dinv[s3]);
        float4 h0 = *(const float4*)(g_h2 + (long long)s0 * 128 + lane * 4);
        float4 h1 = *(const float4*)(g_h2 + (long long)s1 * 128 + lane * 4);
        float4 h2 = *(const float4*)(g_h2 + (long long)s2 * 128 + lane * 4);
        float4 h3 = *(const float4*)(g_h2 + (long long)s3 * 128 + lane * 4);
        acc.x += d0 * h0.x + d1 * h1.x + d2 * h2.x + d3 * h3.x;
        acc.y += d0 * h0.y + d1 * h1.y + d2 * h2.y + d3 * h3.y;
        acc.z += d0 * h0.z + d1 * h1.z + d2 * h2.z + d3 * h3.z;
        acc.w += d0 * h0.w + d1 * h1.w + d2 * h2.w + d3 * h3.w;
    }
    for (; i < end; i++) {
        int s = __ldg(&g_col[i]);
        float dv = __ldg(&g_dinv[s]);
        float4 hv = *(const float4*)(g_h2 + (long long)s * 128 + lane * 4);
        acc.x += dv * hv.x; acc.y += dv * hv.y;
        acc.z += dv * hv.z; acc.w += dv * hv.w;
    }
    float dd = g_dinv[node];
    int c4 = lane * 4;
    float4 bg = *(const float4*)(b_gcn + c4);
    float4 wv = *(const float4*)(bn_w + c4);
    float4 bv = *(const float4*)(bn_b + c4);
    acc.x = elu(acc.x * dd + bg.x) * wv.x + bv.x;
    acc.y = elu(acc.y * dd + bg.y) * wv.y + bv.y;
    acc.z = elu(acc.z * dd + bg.z) * wv.z + bv.z;
    acc.w = elu(acc.w * dd + bg.w) * wv.w + bv.w;
    *(float4*)(g_out2 + (long long)node * 128 + c4) = acc;

    // gate logit + exp
    float4 wg = *(const float4*)(W_gate + c4);
    float p = acc.x * wg.x + acc.y * wg.y + acc.z * wg.z + acc.w * wg.w;
#pragma unroll
    for (int o = 16; o; o >>= 1) p += __shfl_xor_sync(0xffffffffu, p, o);
    if (lane == 0) g_eg[node] = __expf(p + b_gate[0]);
}

// ---------------- pooling + final FC fused; tail re-zeroes g_deg for next launch ----------------
__global__ void k_pool_final(const float* __restrict__ W_fc,
                             const float* __restrict__ b_fc,
                             float* __restrict__ out) {
    __shared__ float red[8];
    __shared__ float s_acc[256];
    __shared__ float s_inv;
    int gph = blockIdx.x;
    int t = threadIdx.x;  // 256
    int lane = t & 31, wrp = t >> 5;
    int beg = g_segstart[gph], end = g_segstart[gph + 1];

    float s = 0.f;
    for (int n = beg + t; n < end; n += 256) s += g_eg[n];
#pragma unroll
    for (int o = 16; o; o >>= 1) s += __shfl_xor_sync(0xffffffffu, s, o);
    if (lane == 0) red[wrp] = s;
    __syncthreads();
    if (t == 0) {
        float tot = 0.f;
#pragma unroll
        for (int i = 0; i < 8; i++) tot += red[i];
        s_inv = 1.f / (tot + 1e-16f);
    }
    __syncthreads();
    float inv = s_inv;

    int half = t >> 7, c = t & 127;
    float acc = 0.f;
    int n = beg + half;
    for (; n + 8 <= end; n += 8) {
        acc += g_eg[n + 0] * g_out2[(long long)(n + 0) * 128 + c];
        acc += g_eg[n + 2] * g_out2[(long long)(n + 2) * 128 + c];
        acc += g_eg[n + 4] * g_out2[(long long)(n + 4) * 128 + c];
        acc += g_eg[n + 6] * g_out2[(long long)(n + 6) * 128 + c];
    }
    for (; n < end; n += 2)
        acc += g_eg[n] * g_out2[(long long)n * 128 + c];
    s_acc[t] = acc;
    __syncthreads();

    if (t < 128) {
        float p = (s_acc[t] + s_acc[t + 128]) * inv * W_fc[t];
#pragma unroll
        for (int o = 16; o; o >>= 1) p += __shfl_xor_sync(0xffffffffu, p, o);
        if (lane == 0) red[wrp] = p;
    }
    __syncthreads();
    if (t == 0) out[gph] = red[0] + red[1] + red[2] + red[3] + b_fc[0];

    // re-zero degree counters so the next launch starts clean (deterministic:
    // globals are zero-init at load; every launch exits with g_deg == 0)
    int gid = gph * 256 + t;
    for (int k = gid; k < NMAX; k += GSEG * 256) g_deg[k] = 0;
}

extern "C" void kernel_launch(void* const* d_in, const int* in_sizes, int n_in,
                              void* d_out, int out_size) {
    const float* x       = (const float*)d_in[0];
    const int*   ei      = (const int*)d_in[1];
    const int*   batch   = (const int*)d_in[2];
    const float* W_gat   = (const float*)d_in[3];
    const float* att_src = (const float*)d_in[4];
    const float* att_dst = (const float*)d_in[5];
    const float* b_gat   = (const float*)d_in[6];
    const float* bn1_w   = (const float*)d_in[7];
    const float* bn1_b   = (const float*)d_in[8];
    const float* W_gcn   = (const float*)d_in[9];
    const float* b_gcn   = (const float*)d_in[10];
    const float* bn2_w   = (const float*)d_in[11];
    const float* bn2_b   = (const float*)d_in[12];
    const float* W_gate  = (const float*)d_in[13];
    const float* b_gate  = (const float*)d_in[14];
    const float* W_fc    = (const float*)d_in[15];
    const float* b_fc    = (const float*)d_in[16];
    float* out = (float*)d_out;

    int N = in_sizes[0] / 128;
    int E = in_sizes[1] / 2;
    if (N > NMAX) N = NMAX;
    if (E > EMAX) E = EMAX;

    float *p_h, *p_out1, *p_h2;
    cudaGetSymbolAddress((void**)&p_h, g_h);
    cudaGetSymbolAddress((void**)&p_out1, g_out1);
    cudaGetSymbolAddress((void**)&p_h2, g_h2);

    // CSR build (g_deg arrives zeroed from previous launch / loader init)
    k_count<<<(E + 255) / 256, 256>>>(ei, E);
    k_scan<<<1, 1024>>>(batch, N);
    k_fill<<<(E + 255) / 256, 256>>>(ei, E);

    // GAT (gemm is launch #4 -> lands in the ncu capture slot)
    gemm128<<<(N + 127) / 128, 256>>>(x, W_gat, p_h, N);
    k_attn<<<(N * 4 + 255) / 256, 256>>>(att_src, att_dst, N);
    k_gat_agg<<<(N * 32 + 255) / 256, 256>>>(b_gat, bn1_w, bn1_b, N);

    // GCN
    gemm128<<<(N + 127) / 128, 256>>>(p_out1, W_gcn, p_h2, N);
    k_gcn_agg<<<(N * 32 + 255) / 256, 256>>>(b_gcn, bn2_w, bn2_b, W_gate, b_gate, N);

    // Pooling + FC (+ deg re-zero)
    k_pool_final<<<GSEG, 256>>>(W_fc, b_fc, out);
}

// round 5
// speedup vs baseline: 1.5617x; 1.5617x over previous
#include <cuda_runtime.h>
#include <math.h>

#define NMAX 50000
#define EMAX 800000
#define GSEG 64
#define STILE 1024   // scan tile (nodes per scan block)

// ---------------- scratch (device globals; zero-initialized at module load) ----------------
__device__ float g_h[NMAX * 128];      // GAT-transformed features
__device__ float g_asrc[NMAX * 4];     // per-node attention logits (src part)
__device__ float g_adst[NMAX * 4];     // per-node attention logits (dst part)
__device__ float g_out1[NMAX * 128];   // GAT output
__device__ float g_h2[NMAX * 128];     // out1 @ W_gcn, pre-scaled by dinv[row]
__device__ float g_out2[NMAX * 128];   // GCN output
__device__ float g_dinv[NMAX];         // 1/sqrt(deg)
__device__ float g_eg[NMAX];           // exp(gate) per node
__device__ int   g_deg[NMAX];          // degree counts (zeroed by tail of pipeline)
__device__ int   g_rowptr[NMAX + 1];   // CSR row pointers (by dst)
__device__ int   g_wpos[NMAX];         // fill cursors
__device__ int   g_col[EMAX + NMAX];   // CSR column (src node ids)
__device__ int   g_tsum[64];           // scan tile sums
__device__ int   g_toff[64];           // scan tile offsets

__device__ __forceinline__ float lrelu(float v) { return fmaxf(v, 0.2f * v); }
__device__ __forceinline__ float elu(float v) { return v > 0.f ? v : __expf(v) - 1.f; }

// ---------------- CSR: count degrees (g_deg is zero on entry every launch) ----------------
__global__ void k_count(const int* __restrict__ ei, int E) {
    int i = blockIdx.x * blockDim.x + threadIdx.x;
    if (i < E) atomicAdd(&g_deg[__ldg(ei + E + i)], 1);
}

// ---------------- scan level A: per-tile sums of (deg+1) ----------------
__global__ void k_scanA(int N) {
    __shared__ int red[8];
    int t = threadIdx.x;  // 256
    int i0 = blockIdx.x * STILE + t * 4;
    int s = 0;
#pragma unroll
    for (int j = 0; j < 4; j++) {
        int i = i0 + j;
        if (i < N) s += g_deg[i] + 1;
    }
#pragma unroll
    for (int o = 16; o; o >>= 1) s += __shfl_down_sync(0xffffffffu, s, o);
    if ((t & 31) == 0) red[t >> 5] = s;
    __syncthreads();
    if (t == 0) {
        int tot = 0;
#pragma unroll
        for (int i = 0; i < 8; i++) tot += red[i];
        g_tsum[blockIdx.x] = tot;
    }
}

// ---------------- scan level B: exclusive scan of tile sums (<=64 tiles) ----------------
__global__ void k_scanB(int ntiles, int N) {
    __shared__ int w0sum;
    int t = threadIdx.x;  // 64
    int own = (t < ntiles) ? g_tsum[t] : 0;
    int v = own;
#pragma unroll
    for (int o = 1; o < 32; o <<= 1) {
        int u = __shfl_up_sync(0xffffffffu, v, o);
        if ((t & 31) >= o) v += u;
    }
    if (t == 31) w0sum = v;
    __syncthreads();
    if (t >= 32) v += w0sum;
    if (t < ntiles) g_toff[t] = v - own;      // exclusive
    if (t == ntiles - 1) g_rowptr[N] = v;     // total
}

// ---------------- scan level C: per-node offsets, self loop, wpos, dinv ----------------
__global__ void k_scanC(int N) {
    __shared__ int sm[256];
    int t = threadIdx.x;  // 256
    int i0 = blockIdx.x * STILE + t * 4;
    int v[4], ts = 0;
#pragma unroll
    for (int j = 0; j < 4; j++) {
        int i = i0 + j;
        v[j] = (i < N) ? g_deg[i] + 1 : 0;
        ts += v[j];
    }
    sm[t] = ts;
    __syncthreads();
    for (int o = 1; o < 256; o <<= 1) {
        int x = (t >= o) ? sm[t - o] : 0;
        __syncthreads();
        sm[t] += x;
        __syncthreads();
    }
    int base = g_toff[blockIdx.x] + sm[t] - ts;  // exclusive prefix
#pragma unroll
    for (int j = 0; j < 4; j++) {
        int i = i0 + j;
        if (i < N) {
            g_rowptr[i] = base;
            g_col[base] = i;        // self loop in slot 0
            g_wpos[i] = base + 1;   // edges fill after
            g_dinv[i] = rsqrtf((float)v[j]);
            base += v[j];
        }
    }
}

__global__ void k_fill(const int* __restrict__ ei, int E) {
    int i = blockIdx.x * blockDim.x + threadIdx.x;
    if (i >= E) return;
    int s = __ldg(ei + i);
    int d = __ldg(ei + E + i);
    int pos = atomicAdd(&g_wpos[d], 1);
    g_col[pos] = s;
}

// ---------------- GEMM: C[N,128] = A[N,128] @ B[128,128] ----------------
// Tile 128 rows x 64 cols, 256 threads, 8x4 per thread. grid = rowblocks*2.
// MODE 0: epilogue computes attention logits (acc IS h) -> g_asrc/g_adst.
// MODE 1: epilogue scales row r by g_dinv[r] (GCN normalization, src side).
template <int MODE>
__global__ __launch_bounds__(256, 4) void gemm_t(
    const float* __restrict__ A, const float* __restrict__ B,
    float* __restrict__ C, int nrows,
    const float* __restrict__ att_src, const float* __restrict__ att_dst) {
    __shared__ float As[8][128];  // [k][row]
    __shared__ float Bs[8][64];   // [k][col within half]
    int tid = threadIdx.x;
    int ty = tid >> 4;            // 0..15
    int tx = tid & 15;            // 0..15
    int rb = blockIdx.x >> 1;
    int ch = blockIdx.x & 1;      // column half
    int row0 = rb * 128;
    int c0 = ch * 64;

    float acc[8][4];
#pragma unroll
    for (int i = 0; i < 8; i++)
#pragma unroll
        for (int j = 0; j < 4; j++) acc[i][j] = 0.f;

    int ar = tid >> 1;            // 0..127
    int ac = (tid & 1) * 4;       // 0 or 4
    int bk = tid >> 4;            // 0..15 (only 0..7 used)
    int bc = (tid & 15) * 4;      // 0..60

    for (int k0 = 0; k0 < 128; k0 += 8) {
        float4 av = make_float4(0.f, 0.f, 0.f, 0.f);
        if (row0 + ar < nrows)
            av = *(const float4*)(A + (long long)(row0 + ar) * 128 + k0 + ac);
        float4 bv = make_float4(0.f, 0.f, 0.f, 0.f);
        if (bk < 8)
            bv = *(const float4*)(B + (long long)(k0 + bk) * 128 + c0 + bc);
        __syncthreads();
        As[ac + 0][ar] = av.x; As[ac + 1][ar] = av.y;
        As[ac + 2][ar] = av.z; As[ac + 3][ar] = av.w;
        if (bk < 8) *(float4*)(&Bs[bk][bc]) = bv;
        __syncthreads();
#pragma unroll
        for (int kk = 0; kk < 8; kk++) {
            float4 a0 = *(const float4*)(&As[kk][ty * 4]);
            float4 a1 = *(const float4*)(&As[kk][ty * 4 + 64]);
            float4 b  = *(const float4*)(&Bs[kk][tx * 4]);
            float a[8] = {a0.x, a0.y, a0.z, a0.w, a1.x, a1.y, a1.z, a1.w};
#pragma unroll
            for (int i = 0; i < 8; i++) {
                acc[i][0] += a[i] * b.x;
                acc[i][1] += a[i] * b.y;
                acc[i][2] += a[i] * b.z;
                acc[i][3] += a[i] * b.w;
            }
        }
    }

    // store (+ dinv scale for MODE 1)
#pragma unroll
    for (int i = 0; i < 8; i++) {
        int r = row0 + ty * 4 + (i < 4 ? i : 60 + i);
        if (r < nrows) {
            float sc = 1.f;
            if (MODE == 1) sc = g_dinv[r];
            *(float4*)(C + (long long)r * 128 + c0 + tx * 4) =
                make_float4(acc[i][0] * sc, acc[i][1] * sc,
                            acc[i][2] * sc, acc[i][3] * sc);
        }
    }

    if (MODE == 0) {
        // attention logits: this block's cols cover heads ch*2 and ch*2+1.
        // thread's 4 cols lie in head hl = tx>>3; within-head offset (tx*4)&31.
        int hl = tx >> 3;
        int head = ch * 2 + hl;
        int co = (tx * 4) & 31;
        float4 as = *(const float4*)(att_src + head * 32 + co);
        float4 ad = *(const float4*)(att_dst + head * 32 + co);
#pragma unroll
        for (int i = 0; i < 8; i++) {
            float ps = acc[i][0] * as.x + acc[i][1] * as.y +
                       acc[i][2] * as.z + acc[i][3] * as.w;
            float pd = acc[i][0] * ad.x + acc[i][1] * ad.y +
                       acc[i][2] * ad.z + acc[i][3] * ad.w;
            // reduce over the 8 lanes of this head group (deterministic)
#pragma unroll
            for (int o = 4; o; o >>= 1) {
                ps += __shfl_down_sync(0xffffffffu, ps, o);
                pd += __shfl_down_sync(0xffffffffu, pd, o);
            }
            if ((tx & 7) == 0) {
                int r = row0 + ty * 4 + (i < 4 ? i : 60 + i);
                if (r < nrows) {
                    g_asrc[r * 4 + head] = ps;
                    g_adst[r * 4 + head] = pd;
                }
            }
        }
    }
}

// ---------------- GAT aggregation: warp per dst node, single pass, MLP=4 ----------------
__global__ void k_gat_agg(const float* __restrict__ b_gat,
                          const float* __restrict__ bn_w,
                          const float* __restrict__ bn_b, int N) {
    int t = blockIdx.x * blockDim.x + threadIdx.x;
    int node = t >> 5, lane = t & 31;
    if (node >= N) return;
    int head = lane >> 3;
    int beg = g_rowptr[node], end = g_rowptr[node + 1];
    float adh = g_adst[node * 4 + head];

    float4 acc = make_float4(0.f, 0.f, 0.f, 0.f);
    float den = 0.f;
    int i = beg;
    for (; i + 4 <= end; i += 4) {
        int s0 = __ldg(&g_col[i + 0]);
        int s1 = __ldg(&g_col[i + 1]);
        int s2 = __ldg(&g_col[i + 2]);
        int s3 = __ldg(&g_col[i + 3]);
        float a0 = __ldg(&g_asrc[s0 * 4 + head]);
        float a1 = __ldg(&g_asrc[s1 * 4 + head]);
        float a2 = __ldg(&g_asrc[s2 * 4 + head]);
        float a3 = __ldg(&g_asrc[s3 * 4 + head]);
        float4 h0 = *(const float4*)(g_h + (long long)s0 * 128 + lane * 4);
        float4 h1 = *(const float4*)(g_h + (long long)s1 * 128 + lane * 4);
        float4 h2 = *(const float4*)(g_h + (long long)s2 * 128 + lane * 4);
        float4 h3 = *(const float4*)(g_h + (long long)s3 * 128 + lane * 4);
        float e0 = __expf(lrelu(a0 + adh));
        float e1 = __expf(lrelu(a1 + adh));
        float e2 = __expf(lrelu(a2 + adh));
        float e3 = __expf(lrelu(a3 + adh));
        den += (e0 + e1) + (e2 + e3);
        acc.x += e0 * h0.x + e1 * h1.x + e2 * h2.x + e3 * h3.x;
        acc.y += e0 * h0.y + e1 * h1.y + e2 * h2.y + e3 * h3.y;
        acc.z += e0 * h0.z + e1 * h1.z + e2 * h2.z + e3 * h3.z;
        acc.w += e0 * h0.w + e1 * h1.w + e2 * h2.w + e3 * h3.w;
    }
    for (; i < end; i++) {
        int s = __ldg(&g_col[i]);
        float a = __ldg(&g_asrc[s * 4 + head]);
        float e = __expf(lrelu(a + adh));
        den += e;
        float4 hv = *(const float4*)(g_h + (long long)s * 128 + lane * 4);
        acc.x += e * hv.x; acc.y += e * hv.y;
        acc.z += e * hv.z; acc.w += e * hv.w;
    }
    float inv = 1.f / (den + 1e-16f);
    int c4 = lane * 4;
    float4 bg = *(const float4*)(b_gat + c4);
    float4 wv = *(const float4*)(bn_w + c4);
    float4 bv = *(const float4*)(bn_b + c4);
    acc.x = elu(acc.x * inv + bg.x) * wv.x + bv.x;
    acc.y = elu(acc.y * inv + bg.y) * wv.y + bv.y;
    acc.z = elu(acc.z * inv + bg.z) * wv.z + bv.z;
    acc.w = elu(acc.w * inv + bg.w) * wv.w + bv.w;
    *(float4*)(g_out1 + (long long)node * 128 + c4) = acc;
}

// ---------------- GCN aggregation + post + gate (h2 pre-scaled by dinv[src]) ----------------
__global__ void k_gcn_agg(const float* __restrict__ b_gcn,
                          const float* __restrict__ bn_w,
                          const float* __restrict__ bn_b,
                          const float* __restrict__ W_gate,
                          const float* __restrict__ b_gate, int N) {
    int t = blockIdx.x * blockDim.x + threadIdx.x;
    int node = t >> 5, lane = t & 31;
    if (node >= N) return;
    int beg = g_rowptr[node], end = g_rowptr[node + 1];

    float4 acc = make_float4(0.f, 0.f, 0.f, 0.f);
    int i = beg;
    for (; i + 4 <= end; i += 4) {
        int s0 = __ldg(&g_col[i + 0]);
        int s1 = __ldg(&g_col[i + 1]);
        int s2 = __ldg(&g_col[i + 2]);
        int s3 = __ldg(&g_col[i + 3]);
        float4 h0 = *(const float4*)(g_h2 + (long long)s0 * 128 + lane * 4);
        float4 h1 = *(const float4*)(g_h2 + (long long)s1 * 128 + lane * 4);
        float4 h2 = *(const float4*)(g_h2 + (long long)s2 * 128 + lane * 4);
        float4 h3 = *(const float4*)(g_h2 + (long long)s3 * 128 + lane * 4);
        acc.x += (h0.x + h1.x) + (h2.x + h3.x);
        acc.y += (h0.y + h1.y) + (h2.y + h3.y);
        acc.z += (h0.z + h1.z) + (h2.z + h3.z);
        acc.w += (h0.w + h1.w) + (h2.w + h3.w);
    }
    for (; i < end; i++) {
        int s = __ldg(&g_col[i]);
        float4 hv = *(const float4*)(g_h2 + (long long)s * 128 + lane * 4);
        acc.x += hv.x; acc.y += hv.y; acc.z += hv.z; acc.w += hv.w;
    }
    float dd = g_dinv[node];
    int c4 = lane * 4;
    float4 bg = *(const float4*)(b_gcn + c4);
    float4 wv = *(const float4*)(bn_w + c4);
    float4 bv = *(const float4*)(bn_b + c4);
    acc.x = elu(acc.x * dd + bg.x) * wv.x + bv.x;
    acc.y = elu(acc.y * dd + bg.y) * wv.y + bv.y;
    acc.z = elu(acc.z * dd + bg.z) * wv.z + bv.z;
    acc.w = elu(acc.w * dd + bg.w) * wv.w + bv.w;
    *(float4*)(g_out2 + (long long)node * 128 + c4) = acc;

    // gate logit + exp
    float4 wg = *(const float4*)(W_gate + c4);
    float p = acc.x * wg.x + acc.y * wg.y + acc.z * wg.z + acc.w * wg.w;
#pragma unroll
    for (int o = 16; o; o >>= 1) p += __shfl_xor_sync(0xffffffffu, p, o);
    if (lane == 0) g_eg[node] = __expf(p + b_gate[0]);
}

// first index i in [0,N) with batch[i] >= key (batch sorted ascending)
__device__ __forceinline__ int lower_bound(const int* __restrict__ batch, int N, int key) {
    int lo = 0, hi = N;
    while (lo < hi) {
        int mid = (lo + hi) >> 1;
        if (__ldg(batch + mid) < key) lo = mid + 1; else hi = mid;
    }
    return lo;
}

// ---------------- pooling + final FC fused; tail re-zeroes g_deg for next launch ----------------
__global__ void k_pool_final(const int* __restrict__ batch,
                             const float* __restrict__ W_fc,
                             const float* __restrict__ b_fc,
                             float* __restrict__ out, int N) {
    __shared__ float red[8];
    __shared__ float s_acc[256];
    __shared__ float s_inv;
    int gph = blockIdx.x;
    int t = threadIdx.x;  // 256
    int lane = t & 31, wrp = t >> 5;
    int beg = lower_bound(batch, N, gph);
    int end = lower_bound(batch, N, gph + 1);

    float s = 0.f;
    for (int n = beg + t; n < end; n += 256) s += g_eg[n];
#pragma unroll
    for (int o = 16; o; o >>= 1) s += __shfl_xor_sync(0xffffffffu, s, o);
    if (lane == 0) red[wrp] = s;
    __syncthreads();
    if (t == 0) {
        float tot = 0.f;
#pragma unroll
        for (int i = 0; i < 8; i++) tot += red[i];
        s_inv = 1.f / (tot + 1e-16f);
    }
    __syncthreads();
    float inv = s_inv;

    int half = t >> 7, c = t & 127;
    float acc = 0.f;
    int n = beg + half;
    for (; n + 8 <= end; n += 8) {
        acc += g_eg[n + 0] * g_out2[(long long)(n + 0) * 128 + c];
        acc += g_eg[n + 2] * g_out2[(long long)(n + 2) * 128 + c];
        acc += g_eg[n + 4] * g_out2[(long long)(n + 4) * 128 + c];
        acc += g_eg[n + 6] * g_out2[(long long)(n + 6) * 128 + c];
    }
    for (; n < end; n += 2)
        acc += g_eg[n] * g_out2[(long long)n * 128 + c];
    s_acc[t] = acc;
    __syncthreads();

    if (t < 128) {
        float p = (s_acc[t] + s_acc[t + 128]) * inv * W_fc[t];
#pragma unroll
        for (int o = 16; o; o >>= 1) p += __shfl_xor_sync(0xffffffffu, p, o);
        if (lane == 0) red[wrp] = p;
    }
    __syncthreads();
    if (t == 0) out[gph] = red[0] + red[1] + red[2] + red[3] + b_fc[0];

    // re-zero degree counters so the next launch starts clean
    int gid = gph * 256 + t;
    for (int k = gid; k < NMAX; k += GSEG * 256) g_deg[k] = 0;
}

extern "C" void kernel_launch(void* const* d_in, const int* in_sizes, int n_in,
                              void* d_out, int out_size) {
    const float* x       = (const float*)d_in[0];
    const int*   ei      = (const int*)d_in[1];
    const int*   batch   = (const int*)d_in[2];
    const float* W_gat   = (const float*)d_in[3];
    const float* att_src = (const float*)d_in[4];
    const float* att_dst = (const float*)d_in[5];
    const float* b_gat   = (const float*)d_in[6];
    const float* bn1_w   = (const float*)d_in[7];
    const float* bn1_b   = (const float*)d_in[8];
    const float* W_gcn   = (const float*)d_in[9];
    const float* b_gcn   = (const float*)d_in[10];
    const float* bn2_w   = (const float*)d_in[11];
    const float* bn2_b   = (const float*)d_in[12];
    const float* W_gate  = (const float*)d_in[13];
    const float* b_gate  = (const float*)d_in[14];
    const float* W_fc    = (const float*)d_in[15];
    const float* b_fc    = (const float*)d_in[16];
    float* out = (float*)d_out;

    int N = in_sizes[0] / 128;
    int E = in_sizes[1] / 2;
    if (N > NMAX) N = NMAX;
    if (E > EMAX) E = EMAX;
    int ntiles = (N + STILE - 1) / STILE;

    float *p_h, *p_out1, *p_h2;
    cudaGetSymbolAddress((void**)&p_h, g_h);
    cudaGetSymbolAddress((void**)&p_out1, g_out1);
    cudaGetSymbolAddress((void**)&p_h2, g_h2);

    int gemm_grid = ((N + 127) / 128) * 2;

    // CSR build (g_deg arrives zeroed) — gemm1 is launch #4 (ncu capture slot)
    k_count<<<(E + 255) / 256, 256>>>(ei, E);
    k_scanA<<<ntiles, 256>>>(N);
    k_scanB<<<1, 64>>>(ntiles, N);
    gemm_t<0><<<gemm_grid, 256>>>(x, W_gat, p_h, N, att_src, att_dst);
    k_scanC<<<ntiles, 256>>>(N);
    k_fill<<<(E + 255) / 256, 256>>>(ei, E);

    // GAT aggregation
    k_gat_agg<<<(N * 32 + 255) / 256, 256>>>(b_gat, bn1_w, bn1_b, N);

    // GCN (h2 pre-scaled by dinv in epilogue)
    gemm_t<1><<<gemm_grid, 256>>>(p_out1, W_gcn, p_h2, N, nullptr, nullptr);
    k_gcn_agg<<<(N * 32 + 255) / 256, 256>>>(b_gcn, bn2_w, bn2_b, W_gate, b_gate, N);

    // Pooling + FC (+ deg re-zero)
    k_pool_final<<<GSEG, 256>>>(batch, W_fc, b_fc, out, N);
}